// round 14
// baseline (speedup 1.0000x reference)
#include <cuda_runtime.h>
#include <cuda_bf16.h>
#include <math.h>
#include <stdint.h>

#define L 2048
#define DE 768
#define DV 64
#define NH 12
#define DMLP 3072
#define VOCAB 32000
#define NLAYERS 4
#define NSEL 75     // 11 head-col0 + 64 cols of head 11
#define YCOLS 80    // padded K for Wo GEMM

typedef __nv_bfloat16 bf16;

// ------------------------- device scratch ----------------------------------
__device__ __align__(256) float g_Y[L * DE];
__device__ __align__(256) float g_zn[L * DE];
__device__ __align__(256) bf16  g_xnb[L * DE];
__device__ __align__(256) bf16  g_znb[L * DE];
__device__ __align__(256) bf16  g_Qb[NH * L * DE];
__device__ __align__(256) bf16  g_Kb[NH * L * DE];
__device__ __align__(256) bf16  g_S[NH * L * L];
__device__ __align__(256) bf16  g_vselT[YCOLS * L];
__device__ __align__(256) bf16  g_WselT[YCOLS * DE];
__device__ __align__(256) float g_bsel[YCOLS];
__device__ __align__(256) bf16  g_ya[L * YCOLS];
__device__ __align__(256) bf16  g_mlp[L * DMLP];
__device__ __align__(256) bf16  g_logits[L * VOCAB];
// bf16 transposed weights: [n][k]
__device__ __align__(256) bf16  g_Wqb[NLAYERS * NH * DE * DE];
__device__ __align__(256) bf16  g_Wkb[NLAYERS * NH * DE * DE];
__device__ __align__(256) bf16  g_Wob[NLAYERS * DE * YCOLS];
__device__ __align__(256) bf16  g_W1b[NLAYERS * DMLP * DE];
__device__ __align__(256) bf16  g_W2b[NLAYERS * DE * DMLP];
__device__ __align__(256) bf16  g_Wub[(long long)VOCAB * DE];

// ------------------------- helpers ----------------------------------------
__device__ __forceinline__ float gelu_tanh(float x) {
    const float c = 0.7978845608028654f;   // sqrt(2/pi)
    float x3 = x * x * x;
    return 0.5f * x * (1.0f + tanhf(c * (x + 0.044715f * x3)));
}

__device__ __forceinline__ void mma_bf16(float* c, const uint32_t* a, const uint32_t* b) {
    asm volatile(
        "mma.sync.aligned.m16n8k16.row.col.f32.bf16.bf16.f32 "
        "{%0,%1,%2,%3}, {%4,%5,%6,%7}, {%8,%9}, {%0,%1,%2,%3};\n"
        : "+f"(c[0]), "+f"(c[1]), "+f"(c[2]), "+f"(c[3])
        : "r"(a[0]), "r"(a[1]), "r"(a[2]), "r"(a[3]), "r"(b[0]), "r"(b[1]));
}

__device__ __forceinline__ void ldsm4(uint32_t* d, uint32_t addr) {
    asm volatile("ldmatrix.sync.aligned.m8n8.x4.shared.b16 {%0,%1,%2,%3}, [%4];"
                 : "=r"(d[0]), "=r"(d[1]), "=r"(d[2]), "=r"(d[3]) : "r"(addr));
}

__device__ __forceinline__ void cpasync16(uint32_t dst, const void* src, int sz) {
    asm volatile("cp.async.cg.shared.global [%0], [%1], 16, %2;\n"
                 :: "r"(dst), "l"(src), "r"(sz));
}

// ===================== hgemm256: 128x256 block, 64x64 warp tiles ============
// For aligned shapes only: M%128==0, N%256==0, K%32==0 (no bounds checks).
// C[M,N] = epilogue(alpha * A @ B^T + bias [+ residuals])
// mode: 0 bias, 1 gelu(bias), 2 bias+resScale*D, 3 bias+resScale*D+D2 (fp32, ld=ldc)
#define T2_ATILE 10240                 // 128 rows * 80 B
#define T2_BTILE 20480                 // 256 rows * 80 B
#define T2_STG   (T2_ATILE + T2_BTILE) // 30720 B per stage
#define T2_STAGES 3
#define T2_SMEM  (T2_STAGES * T2_STG)  // 92160 B

__global__ __launch_bounds__(256, 1)
void hgemm256_kernel(const bf16* __restrict__ A, long long sA,
                     const bf16* __restrict__ B, long long sB,
                     void* __restrict__ Cv, long long sC,
                     const float* __restrict__ bias, long long sBias,
                     const float* __restrict__ D, const float* __restrict__ D2,
                     int M, int N, int K, int lda, int ldb, int ldc,
                     float alpha, float resScale, int mode, int outBf16)
{
    long long z = blockIdx.z;
    A += z * sA;
    B += z * sB;
    if (bias) bias += z * sBias;

    extern __shared__ __align__(16) bf16 dynsmem[];

    const int tid  = threadIdx.x;
    const int warp = tid >> 5;
    const int lane = tid & 31;
    const int g    = lane >> 2;
    const int tg   = lane & 3;
    const int q8   = lane >> 3;
    const int r8   = lane & 7;
    const int wm   = (warp & 1) * 64;      // 2 warps in M
    const int wn   = (warp >> 1) * 64;     // 4 warps in N
    const int row0 = blockIdx.y * 128;
    const int col0 = blockIdx.x * 256;

    const uint32_t smemBase = (uint32_t)__cvta_generic_to_shared(dynsmem);

    float acc[4][8][4];
#pragma unroll
    for (int mi = 0; mi < 4; mi++)
#pragma unroll
        for (int ni = 0; ni < 8; ni++)
#pragma unroll
            for (int r = 0; r < 4; r++) acc[mi][ni][r] = 0.0f;

    const int nT = K >> 5;   // K/32, exact

    // ---- tile loader: A 512 chunks + B 1024 chunks of 16B ----
    auto load_tile = [&](int kt, int buf) {
        const int k0 = kt * 32;
        const uint32_t sb = smemBase + buf * T2_STG;
#pragma unroll
        for (int i = 0; i < 2; i++) {
            int c = tid + i * 256;
            int row = c >> 2, ch = c & 3;
            cpasync16(sb + row * 80 + ch * 16,
                      A + (long long)(row0 + row) * lda + k0 + ch * 8, 16);
        }
#pragma unroll
        for (int i = 0; i < 4; i++) {
            int c = tid + i * 256;
            int row = c >> 2, ch = c & 3;
            cpasync16(sb + T2_ATILE + row * 80 + ch * 16,
                      B + (long long)(col0 + row) * ldb + k0 + ch * 8, 16);
        }
    };

#pragma unroll
    for (int s = 0; s < T2_STAGES - 1; s++) {
        if (s < nT) {
            load_tile(s, s);
            asm volatile("cp.async.commit_group;\n");
        }
    }

    const int aMoff = ((q8 & 1) ? 8 : 0) + r8;   // A: q1,q3 -> +8 rows
    const int aKoff = (q8 & 2) ? 8 : 0;          // A: q2,q3 -> +8 k
    const int bNoff = ((q8 & 2) ? 8 : 0) + r8;   // B: q2,q3 -> +8 n-rows
    const int bKoff = (q8 & 1) ? 8 : 0;          // B: q1,q3 -> +8 k

    for (int kt = 0; kt < nT; kt++) {
        if (kt + T2_STAGES - 1 < nT) {
            load_tile(kt + T2_STAGES - 1, (kt + T2_STAGES - 1) % T2_STAGES);
            asm volatile("cp.async.commit_group;\n");
        }
        int ahead = nT - 1 - kt;
        if (ahead >= 2)      asm volatile("cp.async.wait_group 2;\n");
        else if (ahead == 1) asm volatile("cp.async.wait_group 1;\n");
        else                 asm volatile("cp.async.wait_group 0;\n");
        __syncthreads();

        const uint32_t aB = smemBase + (kt % T2_STAGES) * T2_STG;
        const uint32_t bB = aB + T2_ATILE;
#pragma unroll
        for (int ks = 0; ks < 2; ks++) {
            const int kk = ks * 16;
            uint32_t af[4][4];
            uint32_t bfr[8][2];
#pragma unroll
            for (int mi = 0; mi < 4; mi++)
                ldsm4(af[mi], aB + (wm + mi * 16 + aMoff) * 80 + (kk + aKoff) * 2);
#pragma unroll
            for (int np = 0; np < 4; np++) {
                uint32_t t4[4];
                ldsm4(t4, bB + (wn + np * 16 + bNoff) * 80 + (kk + bKoff) * 2);
                bfr[2 * np][0] = t4[0]; bfr[2 * np][1] = t4[1];
                bfr[2 * np + 1][0] = t4[2]; bfr[2 * np + 1][1] = t4[3];
            }
#pragma unroll
            for (int mi = 0; mi < 4; mi++)
#pragma unroll
                for (int ni = 0; ni < 8; ni++)
                    mma_bf16(acc[mi][ni], af[mi], bfr[ni]);
        }
        __syncthreads();
    }

    // ---- epilogue ----
    bf16*  cb = (bf16*)Cv  + z * sC;
    float* cf = (float*)Cv + z * sC;
#pragma unroll
    for (int mi = 0; mi < 4; mi++) {
#pragma unroll
        for (int rr = 0; rr < 2; rr++) {
            int grow = row0 + wm + mi * 16 + g + rr * 8;
#pragma unroll
            for (int ni = 0; ni < 8; ni++) {
#pragma unroll
                for (int qq = 0; qq < 2; qq++) {
                    int gcol = col0 + wn + ni * 8 + tg * 2 + qq;
                    float v = alpha * acc[mi][ni][rr * 2 + qq];
                    if (bias) v += bias[gcol];
                    if (mode == 1) v = gelu_tanh(v);
                    if (mode >= 2) v += resScale * D[(long long)grow * ldc + gcol];
                    if (mode == 3) v += D2[(long long)grow * ldc + gcol];
                    if (outBf16) cb[(long long)grow * ldc + gcol] = __float2bfloat16(v);
                    else         cf[(long long)grow * ldc + gcol] = v;
                }
            }
        }
    }
}

// ------------------------- bf16 mma.sync GEMM (small/ragged shapes) ---------
#define STAGES   3
#define TILEB    10240
#define SMEM_BYTES (STAGES * TILEB * 2)

__global__ __launch_bounds__(256, 2)
void hgemm_kernel(const bf16* __restrict__ A, long long sA,
                  const bf16* __restrict__ B, long long sB,
                  void* __restrict__ Cv, long long sC,
                  const float* __restrict__ bias, long long sBias,
                  const float* __restrict__ D, const float* __restrict__ D2,
                  int M, int N, int K, int lda, int ldb, int ldc,
                  float alpha, float resScale, int mode,
                  int outBf16, int transC, int ldct)
{
    long long z = blockIdx.z;
    A += z * sA;
    B += z * sB;
    if (bias) bias += z * sBias;

    extern __shared__ __align__(16) bf16 dynsmem[];

    const int tid  = threadIdx.x;
    const int warp = tid >> 5;
    const int lane = tid & 31;
    const int g    = lane >> 2;
    const int tg   = lane & 3;
    const int q8   = lane >> 3;
    const int r8   = lane & 7;
    const int wm   = (warp & 1) * 64;
    const int wn   = (warp >> 1) * 32;
    const int row0 = blockIdx.y * 128;
    const int col0 = blockIdx.x * 128;

    const uint32_t asBase = (uint32_t)__cvta_generic_to_shared(dynsmem);
    const uint32_t bsBase = asBase + STAGES * TILEB;

    float acc[4][4][4];
#pragma unroll
    for (int mi = 0; mi < 4; mi++)
#pragma unroll
        for (int ni = 0; ni < 4; ni++)
#pragma unroll
            for (int r = 0; r < 4; r++) acc[mi][ni][r] = 0.0f;

    const int nT = (K + 31) / 32;

    auto load_tile = [&](int kt, int buf) {
        const int k0 = kt * 32;
#pragma unroll
        for (int i = 0; i < 2; i++) {
            int c = tid + i * 256;
            int row = c >> 2, ch = c & 3;
            int gk = k0 + ch * 8;
            int grow = row0 + row;
            const bf16* src = A + (long long)grow * lda + gk;
            int sz = (grow < M && gk + 8 <= K) ? 16 : 0;
            if (!sz) src = A;
            cpasync16(asBase + buf * TILEB + row * 80 + ch * 16, src, sz);
        }
#pragma unroll
        for (int i = 0; i < 2; i++) {
            int c = tid + i * 256;
            int row = c >> 2, ch = c & 3;
            int gk = k0 + ch * 8;
            int gn = col0 + row;
            const bf16* src = B + (long long)gn * ldb + gk;
            int sz = (gn < N && gk + 8 <= K) ? 16 : 0;
            if (!sz) src = B;
            cpasync16(bsBase + buf * TILEB + row * 80 + ch * 16, src, sz);
        }
    };

#pragma unroll
    for (int s = 0; s < STAGES - 1; s++) {
        if (s < nT) {
            load_tile(s, s);
            asm volatile("cp.async.commit_group;\n");
        }
    }

    const int aMoff = ((q8 & 1) ? 8 : 0) + r8;
    const int aKoff = (q8 & 2) ? 8 : 0;
    const int bNoff = ((q8 & 2) ? 8 : 0) + r8;
    const int bKoff = (q8 & 1) ? 8 : 0;

    for (int kt = 0; kt < nT; kt++) {
        if (kt + STAGES - 1 < nT) {
            load_tile(kt + STAGES - 1, (kt + STAGES - 1) % STAGES);
            asm volatile("cp.async.commit_group;\n");
        }
        int ahead = nT - 1 - kt;
        if (ahead >= 2)      asm volatile("cp.async.wait_group 2;\n");
        else if (ahead == 1) asm volatile("cp.async.wait_group 1;\n");
        else                 asm volatile("cp.async.wait_group 0;\n");
        __syncthreads();

        const uint32_t aB = asBase + (kt % STAGES) * TILEB;
        const uint32_t bB = bsBase + (kt % STAGES) * TILEB;
#pragma unroll
        for (int ks = 0; ks < 2; ks++) {
            const int kk = ks * 16;
            uint32_t af[4][4];
            uint32_t bfr[4][2];
#pragma unroll
            for (int mi = 0; mi < 4; mi++)
                ldsm4(af[mi], aB + (wm + mi * 16 + aMoff) * 80 + (kk + aKoff) * 2);
#pragma unroll
            for (int np = 0; np < 2; np++) {
                uint32_t t4[4];
                ldsm4(t4, bB + (wn + np * 16 + bNoff) * 80 + (kk + bKoff) * 2);
                bfr[2 * np][0] = t4[0]; bfr[2 * np][1] = t4[1];
                bfr[2 * np + 1][0] = t4[2]; bfr[2 * np + 1][1] = t4[3];
            }
#pragma unroll
            for (int mi = 0; mi < 4; mi++)
#pragma unroll
                for (int ni = 0; ni < 4; ni++)
                    mma_bf16(acc[mi][ni], af[mi], bfr[ni]);
        }
        __syncthreads();
    }

#pragma unroll
    for (int mi = 0; mi < 4; mi++) {
#pragma unroll
        for (int rr = 0; rr < 2; rr++) {
            int grow = row0 + wm + mi * 16 + g + rr * 8;
            if (grow >= M) continue;
#pragma unroll
            for (int ni = 0; ni < 4; ni++) {
#pragma unroll
                for (int qq = 0; qq < 2; qq++) {
                    int gcol = col0 + wn + ni * 8 + tg * 2 + qq;
                    if (gcol >= N) continue;
                    float v = alpha * acc[mi][ni][rr * 2 + qq];
                    if (bias) v += bias[gcol];
                    if (mode == 1) v = gelu_tanh(v);
                    if (mode >= 2) v += resScale * D[(long long)grow * ldc + gcol];
                    if (mode == 3) v += D2[(long long)grow * ldc + gcol];
                    if (transC) {
                        ((bf16*)Cv)[(long long)gcol * ldct + grow] = __float2bfloat16(v);
                    } else if (outBf16) {
                        ((bf16*)Cv)[(z * sC) + (long long)grow * ldc + gcol] = __float2bfloat16(v);
                    } else {
                        ((float*)Cv)[(z * sC) + (long long)grow * ldc + gcol] = v;
                    }
                }
            }
        }
    }
}

// ------------------------- transpose + convert: W[K][N] -> Wb[N][Kpad] ------
__global__ void tconv_kernel(const float* __restrict__ in, bf16* __restrict__ out,
                             int Ksrc, int N, int Kpad,
                             long long inStride, long long outStride)
{
    long long zb = blockIdx.z;
    in  += zb * inStride;
    out += zb * outStride;
    __shared__ float tile[32][33];
    int k0 = blockIdx.x * 32, n0 = blockIdx.y * 32;
    int tx = threadIdx.x, ty = threadIdx.y;   // 32 x 8
#pragma unroll
    for (int i = 0; i < 32; i += 8) {
        int k = k0 + ty + i, n = n0 + tx;
        tile[ty + i][tx] = (k < Ksrc && n < N) ? in[(long long)k * N + n] : 0.0f;
    }
    __syncthreads();
#pragma unroll
    for (int i = 0; i < 32; i += 8) {
        int n = n0 + ty + i, k = k0 + tx;
        if (n < N && k < Kpad)
            out[(long long)n * Kpad + k] = __float2bfloat16(tile[tx][ty + i]);
    }
}

// ------------------------- layernorm ---------------------------------------
__global__ void ln_kernel(const float* __restrict__ in, bf16* __restrict__ outB,
                          float* __restrict__ outF,
                          const float* __restrict__ gamma, const float* __restrict__ beta)
{
    int row = blockIdx.x;
    const float* x = in + (long long)row * DE;
    float s = 0.f, s2 = 0.f;
    for (int i = threadIdx.x; i < DE; i += 256) { float v = x[i]; s += v; s2 += v * v; }
    __shared__ float sh1[256], sh2[256];
    sh1[threadIdx.x] = s; sh2[threadIdx.x] = s2;
    __syncthreads();
    for (int off = 128; off > 0; off >>= 1) {
        if (threadIdx.x < off) {
            sh1[threadIdx.x] += sh1[threadIdx.x + off];
            sh2[threadIdx.x] += sh2[threadIdx.x + off];
        }
        __syncthreads();
    }
    float mean = sh1[0] / DE;
    float var  = fmaxf(sh2[0] / DE - mean * mean, 0.0f);
    float sd   = sqrtf(var);
    float inv  = (sd == 0.0f) ? 1.0f : 1.0f / sd;
    for (int i = threadIdx.x; i < DE; i += 256) {
        float v = gamma[i] * ((x[i] - mean) * inv) + beta[i];
        outB[(long long)row * DE + i] = __float2bfloat16(v);
        if (outF) outF[(long long)row * DE + i] = v;
    }
}

// ------------- fused softmax + per-head attention reduction -----------------
__global__ void softmax_attn_kernel(bf16* __restrict__ S, const bf16* __restrict__ vT,
                                    bf16* __restrict__ ya)
{
    int h = blockIdx.y;
    long long row = blockIdx.x;
    uint4* p = (uint4*)(S + ((long long)h * L + row) * L);
    int t = threadIdx.x;
    uint4 v = p[t];
    __nv_bfloat162 h2[4];
    *(uint4*)h2 = v;
    float f[8];
#pragma unroll
    for (int i = 0; i < 4; i++) {
        float2 d = __bfloat1622float2(h2[i]);
        f[2 * i] = d.x; f[2 * i + 1] = d.y;
    }
    __shared__ float sh[256];
    __shared__ float sh2[256];
    float m = f[0];
#pragma unroll
    for (int i = 1; i < 8; i++) m = fmaxf(m, f[i]);
    sh[t] = m; __syncthreads();
    for (int off = 128; off > 0; off >>= 1) {
        if (t < off) sh[t] = fmaxf(sh[t], sh[t + off]);
        __syncthreads();
    }
    m = sh[0]; __syncthreads();

    if (h < NH - 1) {
        const uint4 vb = ((const uint4*)(vT + (long long)h * L))[t];
        __nv_bfloat162 v2[4];
        *(uint4*)v2 = vb;
        float den = 0.f, num = 0.f;
#pragma unroll
        for (int i = 0; i < 4; i++) {
            float2 fv = __bfloat1622float2(v2[i]);
            float e0 = __expf(f[2 * i] - m);
            float e1 = __expf(f[2 * i + 1] - m);
            den += e0 + e1;
            num += e0 * fv.x + e1 * fv.y;
        }
        sh[t] = den; sh2[t] = num; __syncthreads();
        for (int off = 128; off > 0; off >>= 1) {
            if (t < off) { sh[t] += sh[t + off]; sh2[t] += sh2[t + off]; }
            __syncthreads();
        }
        if (t == 0) ya[row * YCOLS + h] = __float2bfloat16(sh2[0] / sh[0]);
    } else {
        float s = 0.f;
#pragma unroll
        for (int i = 0; i < 8; i++) { f[i] = __expf(f[i] - m); s += f[i]; }
        sh[t] = s; __syncthreads();
        for (int off = 128; off > 0; off >>= 1) {
            if (t < off) sh[t] += sh[t + off];
            __syncthreads();
        }
        float invs = 1.0f / sh[0];
#pragma unroll
        for (int i = 0; i < 4; i++)
            h2[i] = __floats2bfloat162_rn(f[2 * i] * invs, f[2 * i + 1] * invs);
        p[t] = *(uint4*)h2;
    }
}

// ------------------------- final softmax: bf16 in, fp32 out -----------------
__global__ void softmax_vocab_kernel(const bf16* __restrict__ in, float* __restrict__ out)
{
    long long row = blockIdx.x;
    const bf16* x = in + row * VOCAB;
    float* o = out + row * VOCAB;
    __shared__ float sh[256];
    int t = threadIdx.x;
    float m = -3.4e38f;
    for (int i = t; i < VOCAB; i += 256) m = fmaxf(m, __bfloat162float(x[i]));
    sh[t] = m; __syncthreads();
    for (int off = 128; off > 0; off >>= 1) {
        if (t < off) sh[t] = fmaxf(sh[t], sh[t + off]);
        __syncthreads();
    }
    m = sh[0]; __syncthreads();
    float s = 0.f;
    for (int i = t; i < VOCAB; i += 256) {
        float e = __expf(__bfloat162float(x[i]) - m);
        o[i] = e; s += e;
    }
    sh[t] = s; __syncthreads();
    for (int off = 128; off > 0; off >>= 1) {
        if (t < off) sh[t] += sh[t + off];
        __syncthreads();
    }
    float invs = 1.0f / sh[0];
    for (int i = t; i < VOCAB; i += 256) o[i] *= invs;
}

// ------------------------- misc --------------------------------------------
__global__ void embed_kernel(const int* __restrict__ x, const float* __restrict__ we,
                             const float* __restrict__ pe, float* __restrict__ Y)
{
    int i = blockIdx.x * blockDim.x + threadIdx.x;
    if (i >= L * DE) return;
    int l = i / DE, d = i % DE;
    Y[i] = we[(long long)x[l] * DE + d] + pe[i];
}

__global__ void pack_wsel_kernel(const float* __restrict__ Wv, const float* __restrict__ bv,
                                 bf16* __restrict__ WselT, float* __restrict__ bsel, int layer)
{
    int i = blockIdx.x * blockDim.x + threadIdx.x;
    if (i < YCOLS * DE) {
        int c = i / DE, d = i % DE;
        float v = 0.0f;
        if (c < NSEL) {
            int h  = (c < NH - 1) ? c : (NH - 1);
            int vc = (c < NH - 1) ? 0 : (c - (NH - 1));
            v = Wv[(((long long)layer * NH + h) * DE + d) * DV + vc];
        }
        WselT[i] = __float2bfloat16(v);
    }
    if (i < YCOLS) {
        float v = 0.0f;
        if (i < NSEL) {
            int h  = (i < NH - 1) ? i : (NH - 1);
            int vc = (i < NH - 1) ? 0 : (i - (NH - 1));
            v = bv[((long long)layer * NH + h) * DV + vc];
        }
        bsel[i] = v;
    }
}

__global__ void zero_ya_pad_kernel(bf16* __restrict__ ya)
{
    int i = blockIdx.x * blockDim.x + threadIdx.x;
    if (i >= L * (YCOLS - NSEL)) return;
    int row = i / (YCOLS - NSEL), j = i % (YCOLS - NSEL);
    ya[(long long)row * YCOLS + NSEL + j] = __float2bfloat16(0.0f);
}

// ------------------------- host side ---------------------------------------
static void gemm(const bf16* A, long long sA, const bf16* B, long long sB,
                 void* C, long long sC, const float* bias, long long sBias,
                 const float* D, const float* D2,
                 int M, int N, int K, int lda, int ldb, int ldc,
                 float alpha, float resScale, int mode, int outBf16, int transC,
                 int ldct, int batch)
{
    dim3 grid((N + 127) / 128, (M + 127) / 128, batch);
    hgemm_kernel<<<grid, 256, SMEM_BYTES>>>(A, sA, B, sB, C, sC, bias, sBias, D, D2,
                                            M, N, K, lda, ldb, ldc, alpha, resScale, mode,
                                            outBf16, transC, ldct);
}

// aligned shapes: M%128==0, N%256==0, K%32==0
static void gemm256(const bf16* A, long long sA, const bf16* B, long long sB,
                    void* C, long long sC, const float* bias, long long sBias,
                    const float* D, const float* D2,
                    int M, int N, int K, int lda, int ldb, int ldc,
                    float alpha, float resScale, int mode, int outBf16, int batch)
{
    dim3 grid(N / 256, M / 128, batch);
    hgemm256_kernel<<<grid, 256, T2_SMEM>>>(A, sA, B, sB, C, sC, bias, sBias, D, D2,
                                            M, N, K, lda, ldb, ldc, alpha, resScale,
                                            mode, outBf16);
}

static void tconv(const float* in, bf16* out, int Ksrc, int N, int Kpad,
                  long long inStride, long long outStride, int batch)
{
    dim3 grid((Kpad + 31) / 32, (N + 31) / 32, batch);
    tconv_kernel<<<grid, dim3(32, 8)>>>(in, out, Ksrc, N, Kpad, inStride, outStride);
}

template <typename T>
static T* sym_addr(T* sym)
{
    void* p = nullptr;
    cudaGetSymbolAddress(&p, (const void*)sym);
    return (T*)p;
}

extern "C" void kernel_launch(void* const* d_in, const int* in_sizes, int n_in,
                              void* d_out, int out_size)
{
    cudaFuncSetAttribute(hgemm_kernel, cudaFuncAttributeMaxDynamicSharedMemorySize,
                         SMEM_BYTES);
    cudaFuncSetAttribute(hgemm256_kernel, cudaFuncAttributeMaxDynamicSharedMemorySize,
                         T2_SMEM);

    const int*   x   = (const int*)  d_in[0];
    const float* we  = (const float*)d_in[1];
    const float* pe  = (const float*)d_in[2];
    const float* Wq  = (const float*)d_in[3];
    const float* bq  = (const float*)d_in[4];
    const float* Wk  = (const float*)d_in[5];
    const float* bk  = (const float*)d_in[6];
    const float* Wv  = (const float*)d_in[7];
    const float* bv  = (const float*)d_in[8];
    const float* Wo  = (const float*)d_in[9];
    const float* bo  = (const float*)d_in[10];
    const float* g1  = (const float*)d_in[11];
    const float* be1 = (const float*)d_in[12];
    const float* g2  = (const float*)d_in[13];
    const float* be2 = (const float*)d_in[14];
    const float* W1  = (const float*)d_in[15];
    const float* bm1 = (const float*)d_in[16];
    const float* W2  = (const float*)d_in[17];
    const float* bm2 = (const float*)d_in[18];
    const float* gf  = (const float*)d_in[19];
    const float* bef = (const float*)d_in[20];
    const float* Wu  = (const float*)d_in[21];
    const float* bu  = (const float*)d_in[22];
    float* out = (float*)d_out;

    float* Y     = sym_addr(g_Y);
    float* zn    = sym_addr(g_zn);
    bf16*  xnb   = sym_addr(g_xnb);
    bf16*  znb   = sym_addr(g_znb);
    bf16*  Qb    = sym_addr(g_Qb);
    bf16*  Kb    = sym_addr(g_Kb);
    bf16*  S     = sym_addr(g_S);
    bf16*  vselT = sym_addr(g_vselT);
    bf16*  WselT = sym_addr(g_WselT);
    float* bsel  = sym_addr(g_bsel);
    bf16*  ya    = sym_addr(g_ya);
    bf16*  mlp   = sym_addr(g_mlp);
    bf16*  lg    = sym_addr(g_logits);
    bf16*  Wqb   = sym_addr(g_Wqb);
    bf16*  Wkb   = sym_addr(g_Wkb);
    bf16*  Wob   = sym_addr(g_Wob);
    bf16*  W1b   = sym_addr(g_W1b);
    bf16*  W2b   = sym_addr(g_W2b);
    bf16*  Wub   = sym_addr(g_Wub);

    const float inv_sqrt_de = 0.03608439182435161f;  // 1/sqrt(768)

    // one-time (per call) weight transpose + bf16 conversion
    tconv(Wq, Wqb, DE, DE, DE, (long long)DE * DE, (long long)DE * DE, NLAYERS * NH);
    tconv(Wk, Wkb, DE, DE, DE, (long long)DE * DE, (long long)DE * DE, NLAYERS * NH);
    tconv(Wo, Wob, NSEL, DE, YCOLS, (long long)(NH * DV) * DE, (long long)DE * YCOLS, NLAYERS);
    tconv(W1, W1b, DE, DMLP, DE, (long long)DE * DMLP, (long long)DMLP * DE, NLAYERS);
    tconv(W2, W2b, DMLP, DE, DMLP, (long long)DMLP * DE, (long long)DE * DMLP, NLAYERS);
    tconv(Wu, Wub, DE, VOCAB, DE, 0, 0, 1);

    embed_kernel<<<(L * DE + 255) / 256, 256>>>(x, we, pe, Y);
    zero_ya_pad_kernel<<<(L * (YCOLS - NSEL) + 255) / 256, 256>>>(ya);

    for (int l = 0; l < NLAYERS; l++) {
        // xn = LN(Y; g1, be1) -> bf16
        ln_kernel<<<L, 256>>>(Y, xnb, nullptr, g1 + l * DE, be1 + l * DE);

        // Q, K projections (batched over heads) — 128x256 path
        gemm256(xnb, 0, Wqb + (long long)l * NH * DE * DE, (long long)DE * DE,
                Qb, (long long)L * DE, bq + (long long)l * NH * DE, DE, nullptr, nullptr,
                L, DE, DE, DE, DE, DE, 1.0f, 0.0f, 0, 1, NH);
        gemm256(xnb, 0, Wkb + (long long)l * NH * DE * DE, (long long)DE * DE,
                Kb, (long long)L * DE, bk + (long long)l * NH * DE, DE, nullptr, nullptr,
                L, DE, DE, DE, DE, DE, 1.0f, 0.0f, 0, 1, NH);

        // packed V projection -> vselT [YCOLS][L] (transposed store) — small path
        pack_wsel_kernel<<<(YCOLS * DE + 255) / 256, 256>>>(Wv, bv, WselT, bsel, l);
        gemm(xnb, 0, WselT, 0, vselT, 0, bsel, 0, nullptr, nullptr,
             L, YCOLS, DE, DE, DE, 0, 1.0f, 0.0f, 0, 1, 1, L, 1);

        // scores = Q @ K^T / sqrt(DE) — 128x256 path (batched over heads)
        gemm256(Qb, (long long)L * DE, Kb, (long long)L * DE,
                S, (long long)L * L, nullptr, 0, nullptr, nullptr,
                L, L, DE, DE, DE, L, inv_sqrt_de, 0.0f, 0, 1, NH);

        // fused softmax + heads 0..10 attention dot; head 11 normalized in place
        softmax_attn_kernel<<<dim3(L, NH), 256>>>(S, vselT, ya);

        // head 11: [L,64] = P_11 @ vselT[11:75]^T — small path
        gemm(S + (long long)(NH - 1) * L * L, 0, vselT + (long long)(NH - 1) * L, 0,
             ya + (NH - 1), 0, nullptr, 0, nullptr, nullptr,
             L, DV, L, L, L, YCOLS, 1.0f, 0.0f, 0, 1, 0, 0, 1);

        // Y = 2*Y + (ya @ Wo^T + bo), K=80 — small path
        gemm(ya, 0, Wob + (long long)l * DE * YCOLS, 0, Y, 0,
             bo + l * DE, 0, Y, nullptr,
             L, DE, YCOLS, YCOLS, YCOLS, DE, 1.0f, 2.0f, 2, 0, 0, 0, 1);

        // zn = LN(Y; g2, be2) -> fp32 + bf16
        ln_kernel<<<L, 256>>>(Y, znb, zn, g2 + l * DE, be2 + l * DE);

        // mlp = gelu(zn @ W1 + bm1) — 128x256 path
        gemm256(znb, 0, W1b + (long long)l * DMLP * DE, 0, mlp, 0,
                bm1 + (long long)l * DMLP, 0, nullptr, nullptr,
                L, DMLP, DE, DE, DE, DMLP, 1.0f, 0.0f, 1, 1, 1);

        // Y = Y + zn + (mlp @ W2 + bm2) — 128x256 path, two-residual epilogue
        gemm256(mlp, 0, W2b + (long long)l * DE * DMLP, 0, Y, 0,
                bm2 + l * DE, 0, Y, zn,
                L, DE, DMLP, DMLP, DMLP, DE, 1.0f, 1.0f, 3, 0, 1);
    }

    // final LN + vocab projection — 128x256 path — + softmax -> fp32 out
    ln_kernel<<<L, 256>>>(Y, xnb, nullptr, gf, bef);
    gemm256(xnb, 0, Wub, 0, lg, 0, bu, 0, nullptr, nullptr,
            L, VOCAB, DE, DE, DE, VOCAB, 1.0f, 0.0f, 0, 1, 1);
    softmax_vocab_kernel<<<L, 256>>>(lg, out);
}

// round 15
// speedup vs baseline: 1.1492x; 1.1492x over previous
#include <cuda_runtime.h>
#include <cuda_bf16.h>
#include <math.h>
#include <stdint.h>

#define L 2048
#define DE 768
#define DV 64
#define NH 12
#define DMLP 3072
#define VOCAB 32000
#define NLAYERS 4
#define NSEL 75     // 11 head-col0 + 64 cols of head 11
#define YCOLS 80    // padded K for Wo GEMM

typedef __nv_bfloat16 bf16;

// ------------------------- device scratch ----------------------------------
__device__ __align__(256) float g_Y[L * DE];
__device__ __align__(256) float g_zn[L * DE];
__device__ __align__(256) bf16  g_xnb[L * DE];
__device__ __align__(256) bf16  g_znb[L * DE];
__device__ __align__(256) bf16  g_Qb[NH * L * DE];
__device__ __align__(256) bf16  g_Kb[NH * L * DE];
__device__ __align__(256) bf16  g_S[NH * L * L];
__device__ __align__(256) bf16  g_vselT[YCOLS * L];
__device__ __align__(256) bf16  g_WselT[YCOLS * DE];
__device__ __align__(256) float g_bsel[YCOLS];
__device__ __align__(256) bf16  g_ya[L * YCOLS];
__device__ __align__(256) bf16  g_mlp[L * DMLP];
__device__ __align__(256) bf16  g_logits[L * VOCAB];
// bf16 transposed weights: [n][k]
__device__ __align__(256) bf16  g_Wqb[NLAYERS * NH * DE * DE];
__device__ __align__(256) bf16  g_Wkb[NLAYERS * NH * DE * DE];
__device__ __align__(256) bf16  g_Wob[NLAYERS * DE * YCOLS];
__device__ __align__(256) bf16  g_W1b[NLAYERS * DMLP * DE];
__device__ __align__(256) bf16  g_W2b[NLAYERS * DE * DMLP];
__device__ __align__(256) bf16  g_Wub[(long long)VOCAB * DE];

// ------------------------- helpers ----------------------------------------
__device__ __forceinline__ float gelu_tanh(float x) {
    const float c = 0.7978845608028654f;   // sqrt(2/pi)
    float x3 = x * x * x;
    return 0.5f * x * (1.0f + tanhf(c * (x + 0.044715f * x3)));
}

__device__ __forceinline__ void mma_bf16(float* c, const uint32_t* a, const uint32_t* b) {
    asm volatile(
        "mma.sync.aligned.m16n8k16.row.col.f32.bf16.bf16.f32 "
        "{%0,%1,%2,%3}, {%4,%5,%6,%7}, {%8,%9}, {%0,%1,%2,%3};\n"
        : "+f"(c[0]), "+f"(c[1]), "+f"(c[2]), "+f"(c[3])
        : "r"(a[0]), "r"(a[1]), "r"(a[2]), "r"(a[3]), "r"(b[0]), "r"(b[1]));
}

__device__ __forceinline__ void ldsm4(uint32_t* d, uint32_t addr) {
    asm volatile("ldmatrix.sync.aligned.m8n8.x4.shared.b16 {%0,%1,%2,%3}, [%4];"
                 : "=r"(d[0]), "=r"(d[1]), "=r"(d[2]), "=r"(d[3]) : "r"(addr));
}

__device__ __forceinline__ void cpasync16(uint32_t dst, const void* src, int sz) {
    asm volatile("cp.async.cg.shared.global [%0], [%1], 16, %2;\n"
                 :: "r"(dst), "l"(src), "r"(sz));
}

// ------------------------- bf16 tensor-core GEMM ----------------------------
// C[M,N] = epilogue(alpha * A @ B^T + bias [+ residuals])
// A: [M][lda] bf16 row-major. B: [N][ldb] bf16 row-major ("transposed").
// mode: 0 = bias, 1 = gelu(bias), 2 = bias + resScale*D,
//       3 = bias + resScale*D + D2        (D, D2 fp32, ld=ldc)
// outBf16: C stored as bf16 (ldc elems) else fp32.
// transC: C stored transposed: Cb[gcol*ldct + grow] (bf16 only).
// Block 128x128x32, 8 warps (warp 64x32), m16n8k16, ldmatrix,
// 3-stage cp.async pipeline in dynamic smem. Occupancy 2.
#define STAGES   3
#define TILEB    10240
#define SMEM_BYTES (STAGES * TILEB * 2)

__global__ __launch_bounds__(256, 2)
void hgemm_kernel(const bf16* __restrict__ A, long long sA,
                  const bf16* __restrict__ B, long long sB,
                  void* __restrict__ Cv, long long sC,
                  const float* __restrict__ bias, long long sBias,
                  const float* __restrict__ D, const float* __restrict__ D2,
                  int M, int N, int K, int lda, int ldb, int ldc,
                  float alpha, float resScale, int mode,
                  int outBf16, int transC, int ldct)
{
    long long z = blockIdx.z;
    A += z * sA;
    B += z * sB;
    if (bias) bias += z * sBias;

    extern __shared__ __align__(16) bf16 dynsmem[];

    const int tid  = threadIdx.x;
    const int warp = tid >> 5;
    const int lane = tid & 31;
    const int g    = lane >> 2;
    const int tg   = lane & 3;
    const int q8   = lane >> 3;
    const int r8   = lane & 7;
    const int wm   = (warp & 1) * 64;
    const int wn   = (warp >> 1) * 32;
    const int row0 = blockIdx.y * 128;
    const int col0 = blockIdx.x * 128;

    const uint32_t asBase = (uint32_t)__cvta_generic_to_shared(dynsmem);
    const uint32_t bsBase = asBase + STAGES * TILEB;

    float acc[4][4][4];
#pragma unroll
    for (int mi = 0; mi < 4; mi++)
#pragma unroll
        for (int ni = 0; ni < 4; ni++)
#pragma unroll
            for (int r = 0; r < 4; r++) acc[mi][ni][r] = 0.0f;

    const int nT = (K + 31) / 32;

    auto load_tile = [&](int kt, int buf) {
        const int k0 = kt * 32;
#pragma unroll
        for (int i = 0; i < 2; i++) {
            int c = tid + i * 256;
            int row = c >> 2, ch = c & 3;
            int gk = k0 + ch * 8;
            int grow = row0 + row;
            const bf16* src = A + (long long)grow * lda + gk;
            int sz = (grow < M && gk + 8 <= K) ? 16 : 0;
            if (!sz) src = A;
            cpasync16(asBase + buf * TILEB + row * 80 + ch * 16, src, sz);
        }
#pragma unroll
        for (int i = 0; i < 2; i++) {
            int c = tid + i * 256;
            int row = c >> 2, ch = c & 3;
            int gk = k0 + ch * 8;
            int gn = col0 + row;
            const bf16* src = B + (long long)gn * ldb + gk;
            int sz = (gn < N && gk + 8 <= K) ? 16 : 0;
            if (!sz) src = B;
            cpasync16(bsBase + buf * TILEB + row * 80 + ch * 16, src, sz);
        }
    };

#pragma unroll
    for (int s = 0; s < STAGES - 1; s++) {
        if (s < nT) {
            load_tile(s, s);
            asm volatile("cp.async.commit_group;\n");
        }
    }

    const int aMoff = ((q8 & 1) ? 8 : 0) + r8;
    const int aKoff = (q8 & 2) ? 8 : 0;
    const int bNoff = ((q8 & 2) ? 8 : 0) + r8;
    const int bKoff = (q8 & 1) ? 8 : 0;

    for (int kt = 0; kt < nT; kt++) {
        if (kt + STAGES - 1 < nT) {
            load_tile(kt + STAGES - 1, (kt + STAGES - 1) % STAGES);
            asm volatile("cp.async.commit_group;\n");
        }
        int ahead = nT - 1 - kt;
        if (ahead >= 2)      asm volatile("cp.async.wait_group 2;\n");
        else if (ahead == 1) asm volatile("cp.async.wait_group 1;\n");
        else                 asm volatile("cp.async.wait_group 0;\n");
        __syncthreads();

        const uint32_t aB = asBase + (kt % STAGES) * TILEB;
        const uint32_t bB = bsBase + (kt % STAGES) * TILEB;
#pragma unroll
        for (int ks = 0; ks < 2; ks++) {
            const int kk = ks * 16;
            uint32_t af[4][4];
            uint32_t bfr[4][2];
#pragma unroll
            for (int mi = 0; mi < 4; mi++)
                ldsm4(af[mi], aB + (wm + mi * 16 + aMoff) * 80 + (kk + aKoff) * 2);
#pragma unroll
            for (int np = 0; np < 2; np++) {
                uint32_t t4[4];
                ldsm4(t4, bB + (wn + np * 16 + bNoff) * 80 + (kk + bKoff) * 2);
                bfr[2 * np][0] = t4[0]; bfr[2 * np][1] = t4[1];
                bfr[2 * np + 1][0] = t4[2]; bfr[2 * np + 1][1] = t4[3];
            }
#pragma unroll
            for (int mi = 0; mi < 4; mi++)
#pragma unroll
                for (int ni = 0; ni < 4; ni++)
                    mma_bf16(acc[mi][ni], af[mi], bfr[ni]);
        }
        __syncthreads();
    }

#pragma unroll
    for (int mi = 0; mi < 4; mi++) {
#pragma unroll
        for (int rr = 0; rr < 2; rr++) {
            int grow = row0 + wm + mi * 16 + g + rr * 8;
            if (grow >= M) continue;
#pragma unroll
            for (int ni = 0; ni < 4; ni++) {
#pragma unroll
                for (int qq = 0; qq < 2; qq++) {
                    int gcol = col0 + wn + ni * 8 + tg * 2 + qq;
                    if (gcol >= N) continue;
                    float v = alpha * acc[mi][ni][rr * 2 + qq];
                    if (bias) v += bias[gcol];
                    if (mode == 1) v = gelu_tanh(v);
                    if (mode >= 2) v += resScale * D[(long long)grow * ldc + gcol];
                    if (mode == 3) v += D2[(long long)grow * ldc + gcol];
                    if (transC) {
                        ((bf16*)Cv)[(long long)gcol * ldct + grow] = __float2bfloat16(v);
                    } else if (outBf16) {
                        ((bf16*)Cv)[(z * sC) + (long long)grow * ldc + gcol] = __float2bfloat16(v);
                    } else {
                        ((float*)Cv)[(z * sC) + (long long)grow * ldc + gcol] = v;
                    }
                }
            }
        }
    }
}

// ------------------------- transpose + convert: W[K][N] -> Wb[N][Kpad] ------
__global__ void tconv_kernel(const float* __restrict__ in, bf16* __restrict__ out,
                             int Ksrc, int N, int Kpad,
                             long long inStride, long long outStride)
{
    long long zb = blockIdx.z;
    in  += zb * inStride;
    out += zb * outStride;
    __shared__ float tile[32][33];
    int k0 = blockIdx.x * 32, n0 = blockIdx.y * 32;
    int tx = threadIdx.x, ty = threadIdx.y;   // 32 x 8
#pragma unroll
    for (int i = 0; i < 32; i += 8) {
        int k = k0 + ty + i, n = n0 + tx;
        tile[ty + i][tx] = (k < Ksrc && n < N) ? in[(long long)k * N + n] : 0.0f;
    }
    __syncthreads();
#pragma unroll
    for (int i = 0; i < 32; i += 8) {
        int n = n0 + ty + i, k = k0 + tx;
        if (n < N && k < Kpad)
            out[(long long)n * Kpad + k] = __float2bfloat16(tile[tx][ty + i]);
    }
}

// ------------------------- layernorm ---------------------------------------
__global__ void ln_kernel(const float* __restrict__ in, bf16* __restrict__ outB,
                          float* __restrict__ outF,
                          const float* __restrict__ gamma, const float* __restrict__ beta)
{
    int row = blockIdx.x;
    const float* x = in + (long long)row * DE;
    float s = 0.f, s2 = 0.f;
    for (int i = threadIdx.x; i < DE; i += 256) { float v = x[i]; s += v; s2 += v * v; }
    __shared__ float sh1[256], sh2[256];
    sh1[threadIdx.x] = s; sh2[threadIdx.x] = s2;
    __syncthreads();
    for (int off = 128; off > 0; off >>= 1) {
        if (threadIdx.x < off) {
            sh1[threadIdx.x] += sh1[threadIdx.x + off];
            sh2[threadIdx.x] += sh2[threadIdx.x + off];
        }
        __syncthreads();
    }
    float mean = sh1[0] / DE;
    float var  = fmaxf(sh2[0] / DE - mean * mean, 0.0f);
    float sd   = sqrtf(var);
    float inv  = (sd == 0.0f) ? 1.0f : 1.0f / sd;
    for (int i = threadIdx.x; i < DE; i += 256) {
        float v = gamma[i] * ((x[i] - mean) * inv) + beta[i];
        outB[(long long)row * DE + i] = __float2bfloat16(v);
        if (outF) outF[(long long)row * DE + i] = v;
    }
}

// ------------- fused softmax + per-head attention reduction -----------------
// One block per (row, head). Reads raw scores S (pre-softmax, already scaled).
// h < 11 : ya[row][h] = sum(exp(s-m)*v_h) / sum(exp(s-m));  S row NOT written.
// h == 11: S row normalized in place (feeds the 64-wide PV GEMM).
__global__ void softmax_attn_kernel(bf16* __restrict__ S, const bf16* __restrict__ vT,
                                    bf16* __restrict__ ya)
{
    int h = blockIdx.y;
    long long row = blockIdx.x;
    uint4* p = (uint4*)(S + ((long long)h * L + row) * L);
    int t = threadIdx.x;
    uint4 v = p[t];
    __nv_bfloat162 h2[4];
    *(uint4*)h2 = v;
    float f[8];
#pragma unroll
    for (int i = 0; i < 4; i++) {
        float2 d = __bfloat1622float2(h2[i]);
        f[2 * i] = d.x; f[2 * i + 1] = d.y;
    }
    __shared__ float sh[256];
    __shared__ float sh2[256];
    float m = f[0];
#pragma unroll
    for (int i = 1; i < 8; i++) m = fmaxf(m, f[i]);
    sh[t] = m; __syncthreads();
    for (int off = 128; off > 0; off >>= 1) {
        if (t < off) sh[t] = fmaxf(sh[t], sh[t + off]);
        __syncthreads();
    }
    m = sh[0]; __syncthreads();

    if (h < NH - 1) {
        const uint4 vb = ((const uint4*)(vT + (long long)h * L))[t];
        __nv_bfloat162 v2[4];
        *(uint4*)v2 = vb;
        float den = 0.f, num = 0.f;
#pragma unroll
        for (int i = 0; i < 4; i++) {
            float2 fv = __bfloat1622float2(v2[i]);
            float e0 = __expf(f[2 * i] - m);
            float e1 = __expf(f[2 * i + 1] - m);
            den += e0 + e1;
            num += e0 * fv.x + e1 * fv.y;
        }
        sh[t] = den; sh2[t] = num; __syncthreads();
        for (int off = 128; off > 0; off >>= 1) {
            if (t < off) { sh[t] += sh[t + off]; sh2[t] += sh2[t + off]; }
            __syncthreads();
        }
        if (t == 0) ya[row * YCOLS + h] = __float2bfloat16(sh2[0] / sh[0]);
    } else {
        float s = 0.f;
#pragma unroll
        for (int i = 0; i < 8; i++) { f[i] = __expf(f[i] - m); s += f[i]; }
        sh[t] = s; __syncthreads();
        for (int off = 128; off > 0; off >>= 1) {
            if (t < off) sh[t] += sh[t + off];
            __syncthreads();
        }
        float invs = 1.0f / sh[0];
#pragma unroll
        for (int i = 0; i < 4; i++)
            h2[i] = __floats2bfloat162_rn(f[2 * i] * invs, f[2 * i + 1] * invs);
        p[t] = *(uint4*)h2;
    }
}

// ------------------------- final softmax: bf16 in, fp32 out -----------------
__global__ void softmax_vocab_kernel(const bf16* __restrict__ in, float* __restrict__ out)
{
    long long row = blockIdx.x;
    const bf16* x = in + row * VOCAB;
    float* o = out + row * VOCAB;
    __shared__ float sh[256];
    int t = threadIdx.x;
    float m = -3.4e38f;
    for (int i = t; i < VOCAB; i += 256) m = fmaxf(m, __bfloat162float(x[i]));
    sh[t] = m; __syncthreads();
    for (int off = 128; off > 0; off >>= 1) {
        if (t < off) sh[t] = fmaxf(sh[t], sh[t + off]);
        __syncthreads();
    }
    m = sh[0]; __syncthreads();
    float s = 0.f;
    for (int i = t; i < VOCAB; i += 256) {
        float e = __expf(__bfloat162float(x[i]) - m);
        o[i] = e; s += e;
    }
    sh[t] = s; __syncthreads();
    for (int off = 128; off > 0; off >>= 1) {
        if (t < off) sh[t] += sh[t + off];
        __syncthreads();
    }
    float invs = 1.0f / sh[0];
    for (int i = t; i < VOCAB; i += 256) o[i] *= invs;
}

// ------------------------- misc --------------------------------------------
__global__ void embed_kernel(const int* __restrict__ x, const float* __restrict__ we,
                             const float* __restrict__ pe, float* __restrict__ Y)
{
    int i = blockIdx.x * blockDim.x + threadIdx.x;
    if (i >= L * DE) return;
    int l = i / DE, d = i % DE;
    Y[i] = we[(long long)x[l] * DE + d] + pe[i];
}

__global__ void pack_wsel_kernel(const float* __restrict__ Wv, const float* __restrict__ bv,
                                 bf16* __restrict__ WselT, float* __restrict__ bsel, int layer)
{
    int i = blockIdx.x * blockDim.x + threadIdx.x;
    if (i < YCOLS * DE) {
        int c = i / DE, d = i % DE;
        float v = 0.0f;
        if (c < NSEL) {
            int h  = (c < NH - 1) ? c : (NH - 1);
            int vc = (c < NH - 1) ? 0 : (c - (NH - 1));
            v = Wv[(((long long)layer * NH + h) * DE + d) * DV + vc];
        }
        WselT[i] = __float2bfloat16(v);
    }
    if (i < YCOLS) {
        float v = 0.0f;
        if (i < NSEL) {
            int h  = (i < NH - 1) ? i : (NH - 1);
            int vc = (i < NH - 1) ? 0 : (i - (NH - 1));
            v = bv[((long long)layer * NH + h) * DV + vc];
        }
        bsel[i] = v;
    }
}

__global__ void zero_ya_pad_kernel(bf16* __restrict__ ya)
{
    int i = blockIdx.x * blockDim.x + threadIdx.x;
    if (i >= L * (YCOLS - NSEL)) return;
    int row = i / (YCOLS - NSEL), j = i % (YCOLS - NSEL);
    ya[(long long)row * YCOLS + NSEL + j] = __float2bfloat16(0.0f);
}

// ------------------------- host side ---------------------------------------
static void gemm(const bf16* A, long long sA, const bf16* B, long long sB,
                 void* C, long long sC, const float* bias, long long sBias,
                 const float* D, const float* D2,
                 int M, int N, int K, int lda, int ldb, int ldc,
                 float alpha, float resScale, int mode, int outBf16, int transC,
                 int ldct, int batch)
{
    dim3 grid((N + 127) / 128, (M + 127) / 128, batch);
    hgemm_kernel<<<grid, 256, SMEM_BYTES>>>(A, sA, B, sB, C, sC, bias, sBias, D, D2,
                                            M, N, K, lda, ldb, ldc, alpha, resScale, mode,
                                            outBf16, transC, ldct);
}

static void tconv(const float* in, bf16* out, int Ksrc, int N, int Kpad,
                  long long inStride, long long outStride, int batch)
{
    dim3 grid((Kpad + 31) / 32, (N + 31) / 32, batch);
    tconv_kernel<<<grid, dim3(32, 8)>>>(in, out, Ksrc, N, Kpad, inStride, outStride);
}

template <typename T>
static T* sym_addr(T* sym)
{
    void* p = nullptr;
    cudaGetSymbolAddress(&p, (const void*)sym);
    return (T*)p;
}

extern "C" void kernel_launch(void* const* d_in, const int* in_sizes, int n_in,
                              void* d_out, int out_size)
{
    cudaFuncSetAttribute(hgemm_kernel, cudaFuncAttributeMaxDynamicSharedMemorySize,
                         SMEM_BYTES);

    const int*   x   = (const int*)  d_in[0];
    const float* we  = (const float*)d_in[1];
    const float* pe  = (const float*)d_in[2];
    const float* Wq  = (const float*)d_in[3];
    const float* bq  = (const float*)d_in[4];
    const float* Wk  = (const float*)d_in[5];
    const float* bk  = (const float*)d_in[6];
    const float* Wv  = (const float*)d_in[7];
    const float* bv  = (const float*)d_in[8];
    const float* Wo  = (const float*)d_in[9];
    const float* bo  = (const float*)d_in[10];
    const float* g1  = (const float*)d_in[11];
    const float* be1 = (const float*)d_in[12];
    const float* g2  = (const float*)d_in[13];
    const float* be2 = (const float*)d_in[14];
    const float* W1  = (const float*)d_in[15];
    const float* bm1 = (const float*)d_in[16];
    const float* W2  = (const float*)d_in[17];
    const float* bm2 = (const float*)d_in[18];
    const float* gf  = (const float*)d_in[19];
    const float* bef = (const float*)d_in[20];
    const float* Wu  = (const float*)d_in[21];
    const float* bu  = (const float*)d_in[22];
    float* out = (float*)d_out;

    float* Y     = sym_addr(g_Y);
    float* zn    = sym_addr(g_zn);
    bf16*  xnb   = sym_addr(g_xnb);
    bf16*  znb   = sym_addr(g_znb);
    bf16*  Qb    = sym_addr(g_Qb);
    bf16*  Kb    = sym_addr(g_Kb);
    bf16*  S     = sym_addr(g_S);
    bf16*  vselT = sym_addr(g_vselT);
    bf16*  WselT = sym_addr(g_WselT);
    float* bsel  = sym_addr(g_bsel);
    bf16*  ya    = sym_addr(g_ya);
    bf16*  mlp   = sym_addr(g_mlp);
    bf16*  lg    = sym_addr(g_logits);
    bf16*  Wqb   = sym_addr(g_Wqb);
    bf16*  Wkb   = sym_addr(g_Wkb);
    bf16*  Wob   = sym_addr(g_Wob);
    bf16*  W1b   = sym_addr(g_W1b);
    bf16*  W2b   = sym_addr(g_W2b);
    bf16*  Wub   = sym_addr(g_Wub);

    const float inv_sqrt_de = 0.03608439182435161f;  // 1/sqrt(768)

    // Launch order chosen so ncu's "-s 5 -c 1" captures the layer-0 Q-projection
    // hgemm (launch index 5) instead of a tconv:
    //   0: embed, 1: tconv Wq, 2: tconv Wk, 3: tconv W1, 4: ln, 5: hgemm Q-proj
    embed_kernel<<<(L * DE + 255) / 256, 256>>>(x, we, pe, Y);                     // 0
    tconv(Wq, Wqb, DE, DE, DE, (long long)DE * DE, (long long)DE * DE, NLAYERS * NH); // 1
    tconv(Wk, Wkb, DE, DE, DE, (long long)DE * DE, (long long)DE * DE, NLAYERS * NH); // 2
    tconv(W1, W1b, DE, DMLP, DE, (long long)DE * DMLP, (long long)DMLP * DE, NLAYERS); // 3
    ln_kernel<<<L, 256>>>(Y, xnb, nullptr, g1, be1);                               // 4

    // 5: Q projection, layer 0  <-- ncu capture target
    gemm(xnb, 0, Wqb, (long long)DE * DE,
         Qb, (long long)L * DE, bq, DE, nullptr, nullptr,
         L, DE, DE, DE, DE, DE, 1.0f, 0.0f, 0, 1, 0, 0, NH);

    // remaining one-time conversions
    tconv(Wo, Wob, NSEL, DE, YCOLS, (long long)(NH * DV) * DE, (long long)DE * YCOLS, NLAYERS);
    tconv(W2, W2b, DMLP, DE, DMLP, (long long)DMLP * DE, (long long)DE * DMLP, NLAYERS);
    tconv(Wu, Wub, DE, VOCAB, DE, 0, 0, 1);
    zero_ya_pad_kernel<<<(L * (YCOLS - NSEL) + 255) / 256, 256>>>(ya);

    for (int l = 0; l < NLAYERS; l++) {
        if (l > 0) {
            // xn = LN(Y; g1, be1) -> bf16 (layer 0 already done above)
            ln_kernel<<<L, 256>>>(Y, xnb, nullptr, g1 + l * DE, be1 + l * DE);
            gemm(xnb, 0, Wqb + (long long)l * NH * DE * DE, (long long)DE * DE,
                 Qb, (long long)L * DE, bq + (long long)l * NH * DE, DE, nullptr, nullptr,
                 L, DE, DE, DE, DE, DE, 1.0f, 0.0f, 0, 1, 0, 0, NH);
        }
        gemm(xnb, 0, Wkb + (long long)l * NH * DE * DE, (long long)DE * DE,
             Kb, (long long)L * DE, bk + (long long)l * NH * DE, DE, nullptr, nullptr,
             L, DE, DE, DE, DE, DE, 1.0f, 0.0f, 0, 1, 0, 0, NH);

        // packed V projection -> vselT [YCOLS][L] (transposed store)
        pack_wsel_kernel<<<(YCOLS * DE + 255) / 256, 256>>>(Wv, bv, WselT, bsel, l);
        gemm(xnb, 0, WselT, 0, vselT, 0, bsel, 0, nullptr, nullptr,
             L, YCOLS, DE, DE, DE, 0, 1.0f, 0.0f, 0, 1, 1, L, 1);

        // scores = Q @ K^T / sqrt(DE) -> bf16 S (raw, pre-softmax)
        gemm(Qb, (long long)L * DE, Kb, (long long)L * DE,
             S, (long long)L * L, nullptr, 0, nullptr, nullptr,
             L, L, DE, DE, DE, L, inv_sqrt_de, 0.0f, 0, 1, 0, 0, NH);

        // fused softmax + heads 0..10 attention dot; head 11 normalized in place
        softmax_attn_kernel<<<dim3(L, NH), 256>>>(S, vselT, ya);

        // head 11: [L,64] = P_11 @ vselT[11:75]^T
        gemm(S + (long long)(NH - 1) * L * L, 0, vselT + (long long)(NH - 1) * L, 0,
             ya + (NH - 1), 0, nullptr, 0, nullptr, nullptr,
             L, DV, L, L, L, YCOLS, 1.0f, 0.0f, 0, 1, 0, 0, 1);

        // Y = 2*Y + (ya @ Wo^T + bo), K = 80 (cols 75..79 of ya are zero)
        gemm(ya, 0, Wob + (long long)l * DE * YCOLS, 0, Y, 0,
             bo + l * DE, 0, Y, nullptr,
             L, DE, YCOLS, YCOLS, YCOLS, DE, 1.0f, 2.0f, 2, 0, 0, 0, 1);

        // zn = LN(Y; g2, be2) -> fp32 + bf16
        ln_kernel<<<L, 256>>>(Y, znb, zn, g2 + l * DE, be2 + l * DE);

        // mlp = gelu(zn @ W1 + bm1) -> bf16
        gemm(znb, 0, W1b + (long long)l * DMLP * DE, 0, mlp, 0,
             bm1 + (long long)l * DMLP, 0, nullptr, nullptr,
             L, DMLP, DE, DE, DE, DMLP, 1.0f, 0.0f, 1, 1, 0, 0, 1);

        // Y = Y + zn + (mlp @ W2 + bm2)   (two-residual epilogue, mode 3)
        gemm(mlp, 0, W2b + (long long)l * DE * DMLP, 0, Y, 0,
             bm2 + l * DE, 0, Y, zn,
             L, DE, DMLP, DMLP, DMLP, DE, 1.0f, 1.0f, 3, 0, 0, 0, 1);
    }

    // final LN + vocab projection (bf16 logits) + softmax -> fp32 out
    ln_kernel<<<L, 256>>>(Y, xnb, nullptr, gf, bef);
    gemm(xnb, 0, Wub, 0, lg, 0, bu, 0, nullptr, nullptr,
         L, VOCAB, DE, DE, DE, VOCAB, 1.0f, 0.0f, 0, 1, 0, 0, 1);
    softmax_vocab_kernel<<<L, 256>>>(lg, out);
}

// round 17
// speedup vs baseline: 1.2279x; 1.0685x over previous
#include <cuda_runtime.h>
#include <cuda_bf16.h>
#include <math.h>
#include <stdint.h>

#define L 2048
#define DE 768
#define DV 64
#define NH 12
#define DMLP 3072
#define VOCAB 32000
#define NLAYERS 4
#define NSEL 75     // 11 head-col0 + 64 cols of head 11
#define YCOLS 80    // padded K for Wo GEMM

typedef __nv_bfloat16 bf16;

// ------------------------- device scratch ----------------------------------
__device__ __align__(256) float g_Y[L * DE];
__device__ __align__(256) float g_zn[L * DE];
__device__ __align__(256) bf16  g_xnb[L * DE];
__device__ __align__(256) bf16  g_znb[L * DE];
__device__ __align__(256) bf16  g_Pb[NH * L * DE];          // P = xn @ M per head
__device__ __align__(256) bf16  g_S[NH * L * L];
__device__ __align__(256) bf16  g_vselT[YCOLS * L];
__device__ __align__(256) bf16  g_WselT[YCOLS * DE];
__device__ __align__(256) float g_bsel[YCOLS];
__device__ __align__(256) bf16  g_ya[L * YCOLS];
__device__ __align__(256) bf16  g_mlp[L * DMLP];
__device__ __align__(256) bf16  g_logits[L * VOCAB];
// bf16 weights
__device__ __align__(256) bf16  g_Wqc[NLAYERS * NH * DE * DE];  // Wq, original [d][e] layout
__device__ __align__(256) bf16  g_Wkc[NLAYERS * NH * DE * DE];  // Wk, original [d][e] layout
__device__ __align__(256) bf16  g_Mt[NLAYERS * NH * DE * DE];   // Mt[d'][d] = sum_e Wk[d'][e]Wq[d][e]
__device__ __align__(256) float g_w[NLAYERS * NH * DE];         // w = Wk @ bq per (layer,head)
__device__ __align__(256) float g_c[NH * L];                    // c[h][m] per current layer
// transposed bf16 weights [n][k] for the remaining GEMMs
__device__ __align__(256) bf16  g_Wob[NLAYERS * DE * YCOLS];
__device__ __align__(256) bf16  g_W1b[NLAYERS * DMLP * DE];
__device__ __align__(256) bf16  g_W2b[NLAYERS * DE * DMLP];
__device__ __align__(256) bf16  g_Wub[(long long)VOCAB * DE];

// ------------------------- helpers ----------------------------------------
__device__ __forceinline__ float gelu_tanh(float x) {
    const float c = 0.7978845608028654f;   // sqrt(2/pi)
    float x3 = x * x * x;
    return 0.5f * x * (1.0f + tanhf(c * (x + 0.044715f * x3)));
}

__device__ __forceinline__ void mma_bf16(float* c, const uint32_t* a, const uint32_t* b) {
    asm volatile(
        "mma.sync.aligned.m16n8k16.row.col.f32.bf16.bf16.f32 "
        "{%0,%1,%2,%3}, {%4,%5,%6,%7}, {%8,%9}, {%0,%1,%2,%3};\n"
        : "+f"(c[0]), "+f"(c[1]), "+f"(c[2]), "+f"(c[3])
        : "r"(a[0]), "r"(a[1]), "r"(a[2]), "r"(a[3]), "r"(b[0]), "r"(b[1]));
}

__device__ __forceinline__ void ldsm4(uint32_t* d, uint32_t addr) {
    asm volatile("ldmatrix.sync.aligned.m8n8.x4.shared.b16 {%0,%1,%2,%3}, [%4];"
                 : "=r"(d[0]), "=r"(d[1]), "=r"(d[2]), "=r"(d[3]) : "r"(addr));
}

__device__ __forceinline__ void cpasync16(uint32_t dst, const void* src, int sz) {
    asm volatile("cp.async.cg.shared.global [%0], [%1], 16, %2;\n"
                 :: "r"(dst), "l"(src), "r"(sz));
}

// ------------------------- bf16 tensor-core GEMM ----------------------------
// C[M,N] = epilogue(alpha * A @ B^T + bias [+ residuals])
// Block 128x128x32, 8 warps (warp 64x32), m16n8k16, ldmatrix,
// 3-stage cp.async pipeline in dynamic smem. Occupancy 2.
#define STAGES   3
#define TILEB    10240
#define SMEM_BYTES (STAGES * TILEB * 2)

__global__ __launch_bounds__(256, 2)
void hgemm_kernel(const bf16* __restrict__ A, long long sA,
                  const bf16* __restrict__ B, long long sB,
                  void* __restrict__ Cv, long long sC,
                  const float* __restrict__ bias, long long sBias,
                  const float* __restrict__ D, const float* __restrict__ D2,
                  int M, int N, int K, int lda, int ldb, int ldc,
                  float alpha, float resScale, int mode,
                  int outBf16, int transC, int ldct)
{
    long long z = blockIdx.z;
    A += z * sA;
    B += z * sB;
    if (bias) bias += z * sBias;

    extern __shared__ __align__(16) bf16 dynsmem[];

    const int tid  = threadIdx.x;
    const int warp = tid >> 5;
    const int lane = tid & 31;
    const int g    = lane >> 2;
    const int tg   = lane & 3;
    const int q8   = lane >> 3;
    const int r8   = lane & 7;
    const int wm   = (warp & 1) * 64;
    const int wn   = (warp >> 1) * 32;
    const int row0 = blockIdx.y * 128;
    const int col0 = blockIdx.x * 128;

    const uint32_t asBase = (uint32_t)__cvta_generic_to_shared(dynsmem);
    const uint32_t bsBase = asBase + STAGES * TILEB;

    float acc[4][4][4];
#pragma unroll
    for (int mi = 0; mi < 4; mi++)
#pragma unroll
        for (int ni = 0; ni < 4; ni++)
#pragma unroll
            for (int r = 0; r < 4; r++) acc[mi][ni][r] = 0.0f;

    const int nT = (K + 31) / 32;

    auto load_tile = [&](int kt, int buf) {
        const int k0 = kt * 32;
#pragma unroll
        for (int i = 0; i < 2; i++) {
            int c = tid + i * 256;
            int row = c >> 2, ch = c & 3;
            int gk = k0 + ch * 8;
            int grow = row0 + row;
            const bf16* src = A + (long long)grow * lda + gk;
            int sz = (grow < M && gk + 8 <= K) ? 16 : 0;
            if (!sz) src = A;
            cpasync16(asBase + buf * TILEB + row * 80 + ch * 16, src, sz);
        }
#pragma unroll
        for (int i = 0; i < 2; i++) {
            int c = tid + i * 256;
            int row = c >> 2, ch = c & 3;
            int gk = k0 + ch * 8;
            int gn = col0 + row;
            const bf16* src = B + (long long)gn * ldb + gk;
            int sz = (gn < N && gk + 8 <= K) ? 16 : 0;
            if (!sz) src = B;
            cpasync16(bsBase + buf * TILEB + row * 80 + ch * 16, src, sz);
        }
    };

#pragma unroll
    for (int s = 0; s < STAGES - 1; s++) {
        if (s < nT) {
            load_tile(s, s);
            asm volatile("cp.async.commit_group;\n");
        }
    }

    const int aMoff = ((q8 & 1) ? 8 : 0) + r8;
    const int aKoff = (q8 & 2) ? 8 : 0;
    const int bNoff = ((q8 & 2) ? 8 : 0) + r8;
    const int bKoff = (q8 & 1) ? 8 : 0;

    for (int kt = 0; kt < nT; kt++) {
        if (kt + STAGES - 1 < nT) {
            load_tile(kt + STAGES - 1, (kt + STAGES - 1) % STAGES);
            asm volatile("cp.async.commit_group;\n");
        }
        int ahead = nT - 1 - kt;
        if (ahead >= 2)      asm volatile("cp.async.wait_group 2;\n");
        else if (ahead == 1) asm volatile("cp.async.wait_group 1;\n");
        else                 asm volatile("cp.async.wait_group 0;\n");
        __syncthreads();

        const uint32_t aB = asBase + (kt % STAGES) * TILEB;
        const uint32_t bB = bsBase + (kt % STAGES) * TILEB;
#pragma unroll
        for (int ks = 0; ks < 2; ks++) {
            const int kk = ks * 16;
            uint32_t af[4][4];
            uint32_t bfr[4][2];
#pragma unroll
            for (int mi = 0; mi < 4; mi++)
                ldsm4(af[mi], aB + (wm + mi * 16 + aMoff) * 80 + (kk + aKoff) * 2);
#pragma unroll
            for (int np = 0; np < 2; np++) {
                uint32_t t4[4];
                ldsm4(t4, bB + (wn + np * 16 + bNoff) * 80 + (kk + bKoff) * 2);
                bfr[2 * np][0] = t4[0]; bfr[2 * np][1] = t4[1];
                bfr[2 * np + 1][0] = t4[2]; bfr[2 * np + 1][1] = t4[3];
            }
#pragma unroll
            for (int mi = 0; mi < 4; mi++)
#pragma unroll
                for (int ni = 0; ni < 4; ni++)
                    mma_bf16(acc[mi][ni], af[mi], bfr[ni]);
        }
        __syncthreads();
    }

#pragma unroll
    for (int mi = 0; mi < 4; mi++) {
#pragma unroll
        for (int rr = 0; rr < 2; rr++) {
            int grow = row0 + wm + mi * 16 + g + rr * 8;
            if (grow >= M) continue;
#pragma unroll
            for (int ni = 0; ni < 4; ni++) {
#pragma unroll
                for (int qq = 0; qq < 2; qq++) {
                    int gcol = col0 + wn + ni * 8 + tg * 2 + qq;
                    if (gcol >= N) continue;
                    float v = alpha * acc[mi][ni][rr * 2 + qq];
                    if (bias) v += bias[gcol];
                    if (mode == 1) v = gelu_tanh(v);
                    if (mode >= 2) v += resScale * D[(long long)grow * ldc + gcol];
                    if (mode == 3) v += D2[(long long)grow * ldc + gcol];
                    if (transC) {
                        ((bf16*)Cv)[(long long)gcol * ldct + grow] = __float2bfloat16(v);
                    } else if (outBf16) {
                        ((bf16*)Cv)[(z * sC) + (long long)grow * ldc + gcol] = __float2bfloat16(v);
                    } else {
                        ((float*)Cv)[(z * sC) + (long long)grow * ldc + gcol] = v;
                    }
                }
            }
        }
    }
}

// ------------------------- transpose + convert: W[K][N] -> Wb[N][Kpad] ------
__global__ void tconv_kernel(const float* __restrict__ in, bf16* __restrict__ out,
                             int Ksrc, int N, int Kpad,
                             long long inStride, long long outStride)
{
    long long zb = blockIdx.z;
    in  += zb * inStride;
    out += zb * outStride;
    __shared__ float tile[32][33];
    int k0 = blockIdx.x * 32, n0 = blockIdx.y * 32;
    int tx = threadIdx.x, ty = threadIdx.y;   // 32 x 8
#pragma unroll
    for (int i = 0; i < 32; i += 8) {
        int k = k0 + ty + i, n = n0 + tx;
        tile[ty + i][tx] = (k < Ksrc && n < N) ? in[(long long)k * N + n] : 0.0f;
    }
    __syncthreads();
#pragma unroll
    for (int i = 0; i < 32; i += 8) {
        int n = n0 + ty + i, k = k0 + tx;
        if (n < N && k < Kpad)
            out[(long long)n * Kpad + k] = __float2bfloat16(tile[tx][ty + i]);
    }
}

// ------------------------- flat fp32 -> bf16 convert ------------------------
__global__ void convf2b_kernel(const float* __restrict__ in, bf16* __restrict__ out,
                               long long n)
{
    long long i = ((long long)blockIdx.x * blockDim.x + threadIdx.x) * 4;
    if (i >= n) return;
    float4 v = *(const float4*)(in + i);
    out[i]     = __float2bfloat16(v.x);
    out[i + 1] = __float2bfloat16(v.y);
    out[i + 2] = __float2bfloat16(v.z);
    out[i + 3] = __float2bfloat16(v.w);
}

// ---------------- w = Wk @ bq per (layer,head): one warp per output row -----
__global__ void wvec_kernel(const float* __restrict__ Wk, const float* __restrict__ bq,
                            float* __restrict__ w)
{
    int r = blockIdx.x * 8 + (threadIdx.x >> 5);   // row = lh*DE + d
    int lane = threadIdx.x & 31;
    if (r >= NLAYERS * NH * DE) return;
    int lh = r / DE;
    const float* row = Wk + (long long)r * DE;
    const float* b   = bq + (long long)lh * DE;
    float s = 0.f;
    for (int e = lane; e < DE; e += 32) s += row[e] * b[e];
#pragma unroll
    for (int off = 16; off > 0; off >>= 1)
        s += __shfl_down_sync(0xffffffffu, s, off);
    if (lane == 0) w[r] = s;
}

// ---------------- c[h][m] = inv_sqrt_de * xn_m . w_h  (per layer) -----------
__global__ void cvec_kernel(const bf16* __restrict__ xnb, const float* __restrict__ w,
                            float* __restrict__ c)
{
    int m = blockIdx.x;
    int h = threadIdx.x >> 5;       // 12 warps
    int lane = threadIdx.x & 31;
    const bf16*  xr = xnb + (long long)m * DE;
    const float* wr = w + (long long)h * DE;
    float s = 0.f;
    for (int e = lane; e < DE; e += 32)
        s += __bfloat162float(xr[e]) * wr[e];
#pragma unroll
    for (int off = 16; off > 0; off >>= 1)
        s += __shfl_down_sync(0xffffffffu, s, off);
    if (lane == 0) c[(long long)h * L + m] = 0.03608439182435161f * s;
}

// ------------------------- layernorm ---------------------------------------
__global__ void ln_kernel(const float* __restrict__ in, bf16* __restrict__ outB,
                          float* __restrict__ outF,
                          const float* __restrict__ gamma, const float* __restrict__ beta)
{
    int row = blockIdx.x;
    const float* x = in + (long long)row * DE;
    float s = 0.f, s2 = 0.f;
    for (int i = threadIdx.x; i < DE; i += 256) { float v = x[i]; s += v; s2 += v * v; }
    __shared__ float sh1[256], sh2[256];
    sh1[threadIdx.x] = s; sh2[threadIdx.x] = s2;
    __syncthreads();
    for (int off = 128; off > 0; off >>= 1) {
        if (threadIdx.x < off) {
            sh1[threadIdx.x] += sh1[threadIdx.x + off];
            sh2[threadIdx.x] += sh2[threadIdx.x + off];
        }
        __syncthreads();
    }
    float mean = sh1[0] / DE;
    float var  = fmaxf(sh2[0] / DE - mean * mean, 0.0f);
    float sd   = sqrtf(var);
    float inv  = (sd == 0.0f) ? 1.0f : 1.0f / sd;
    for (int i = threadIdx.x; i < DE; i += 256) {
        float v = gamma[i] * ((x[i] - mean) * inv) + beta[i];
        outB[(long long)row * DE + i] = __float2bfloat16(v);
        if (outF) outF[(long long)row * DE + i] = v;
    }
}

// ------------- fused softmax + per-head attention reduction -----------------
// Scores in S are bilinear-only; the column bias term c[h][m] is added here.
// h < 11 : ya[row][h] = sum(exp(s-m)*v_h) / sum(exp(s-m));  S row NOT written.
// h == 11: S row normalized in place (feeds the 64-wide PV GEMM).
__global__ void softmax_attn_kernel(bf16* __restrict__ S, const bf16* __restrict__ vT,
                                    const float* __restrict__ cvec,
                                    bf16* __restrict__ ya)
{
    int h = blockIdx.y;
    long long row = blockIdx.x;
    uint4* p = (uint4*)(S + ((long long)h * L + row) * L);
    int t = threadIdx.x;
    uint4 v = p[t];
    __nv_bfloat162 h2[4];
    *(uint4*)h2 = v;
    float f[8];
#pragma unroll
    for (int i = 0; i < 4; i++) {
        float2 d = __bfloat1622float2(h2[i]);
        f[2 * i] = d.x; f[2 * i + 1] = d.y;
    }
    // add column bias term c[h][m]
    {
        const float4* cp = (const float4*)(cvec + (long long)h * L);
        float4 c0 = cp[t * 2], c1 = cp[t * 2 + 1];
        f[0] += c0.x; f[1] += c0.y; f[2] += c0.z; f[3] += c0.w;
        f[4] += c1.x; f[5] += c1.y; f[6] += c1.z; f[7] += c1.w;
    }
    __shared__ float sh[256];
    __shared__ float sh2[256];
    float m = f[0];
#pragma unroll
    for (int i = 1; i < 8; i++) m = fmaxf(m, f[i]);
    sh[t] = m; __syncthreads();
    for (int off = 128; off > 0; off >>= 1) {
        if (t < off) sh[t] = fmaxf(sh[t], sh[t + off]);
        __syncthreads();
    }
    m = sh[0]; __syncthreads();

    if (h < NH - 1) {
        const uint4 vb = ((const uint4*)(vT + (long long)h * L))[t];
        __nv_bfloat162 v2[4];
        *(uint4*)v2 = vb;
        float den = 0.f, num = 0.f;
#pragma unroll
        for (int i = 0; i < 4; i++) {
            float2 fv = __bfloat1622float2(v2[i]);
            float e0 = __expf(f[2 * i] - m);
            float e1 = __expf(f[2 * i + 1] - m);
            den += e0 + e1;
            num += e0 * fv.x + e1 * fv.y;
        }
        sh[t] = den; sh2[t] = num; __syncthreads();
        for (int off = 128; off > 0; off >>= 1) {
            if (t < off) { sh[t] += sh[t + off]; sh2[t] += sh2[t + off]; }
            __syncthreads();
        }
        if (t == 0) ya[row * YCOLS + h] = __float2bfloat16(sh2[0] / sh[0]);
    } else {
        float s = 0.f;
#pragma unroll
        for (int i = 0; i < 8; i++) { f[i] = __expf(f[i] - m); s += f[i]; }
        sh[t] = s; __syncthreads();
        for (int off = 128; off > 0; off >>= 1) {
            if (t < off) sh[t] += sh[t + off];
            __syncthreads();
        }
        float invs = 1.0f / sh[0];
#pragma unroll
        for (int i = 0; i < 4; i++)
            h2[i] = __floats2bfloat162_rn(f[2 * i] * invs, f[2 * i + 1] * invs);
        p[t] = *(uint4*)h2;
    }
}

// ------------------------- final softmax: bf16 in, fp32 out -----------------
__global__ void softmax_vocab_kernel(const bf16* __restrict__ in, float* __restrict__ out)
{
    long long row = blockIdx.x;
    const bf16* x = in + row * VOCAB;
    float* o = out + row * VOCAB;
    __shared__ float sh[256];
    int t = threadIdx.x;
    float m = -3.4e38f;
    for (int i = t; i < VOCAB; i += 256) m = fmaxf(m, __bfloat162float(x[i]));
    sh[t] = m; __syncthreads();
    for (int off = 128; off > 0; off >>= 1) {
        if (t < off) sh[t] = fmaxf(sh[t], sh[t + off]);
        __syncthreads();
    }
    m = sh[0]; __syncthreads();
    float s = 0.f;
    for (int i = t; i < VOCAB; i += 256) {
        float e = __expf(__bfloat162float(x[i]) - m);
        o[i] = e; s += e;
    }
    sh[t] = s; __syncthreads();
    for (int off = 128; off > 0; off >>= 1) {
        if (t < off) sh[t] += sh[t + off];
        __syncthreads();
    }
    float invs = 1.0f / sh[0];
    for (int i = t; i < VOCAB; i += 256) o[i] *= invs;
}

// ------------------------- misc --------------------------------------------
__global__ void embed_kernel(const int* __restrict__ x, const float* __restrict__ we,
                             const float* __restrict__ pe, float* __restrict__ Y)
{
    int i = blockIdx.x * blockDim.x + threadIdx.x;
    if (i >= L * DE) return;
    int l = i / DE, d = i % DE;
    Y[i] = we[(long long)x[l] * DE + d] + pe[i];
}

__global__ void pack_wsel_kernel(const float* __restrict__ Wv, const float* __restrict__ bv,
                                 bf16* __restrict__ WselT, float* __restrict__ bsel, int layer)
{
    int i = blockIdx.x * blockDim.x + threadIdx.x;
    if (i < YCOLS * DE) {
        int c = i / DE, d = i % DE;
        float v = 0.0f;
        if (c < NSEL) {
            int h  = (c < NH - 1) ? c : (NH - 1);
            int vc = (c < NH - 1) ? 0 : (c - (NH - 1));
            v = Wv[(((long long)layer * NH + h) * DE + d) * DV + vc];
        }
        WselT[i] = __float2bfloat16(v);
    }
    if (i < YCOLS) {
        float v = 0.0f;
        if (i < NSEL) {
            int h  = (i < NH - 1) ? i : (NH - 1);
            int vc = (i < NH - 1) ? 0 : (i - (NH - 1));
            v = bv[((long long)layer * NH + h) * DV + vc];
        }
        bsel[i] = v;
    }
}

__global__ void zero_ya_pad_kernel(bf16* __restrict__ ya)
{
    int i = blockIdx.x * blockDim.x + threadIdx.x;
    if (i >= L * (YCOLS - NSEL)) return;
    int row = i / (YCOLS - NSEL), j = i % (YCOLS - NSEL);
    ya[(long long)row * YCOLS + NSEL + j] = __float2bfloat16(0.0f);
}

// ------------------------- host side ---------------------------------------
static void gemm(const bf16* A, long long sA, const bf16* B, long long sB,
                 void* C, long long sC, const float* bias, long long sBias,
                 const float* D, const float* D2,
                 int M, int N, int K, int lda, int ldb, int ldc,
                 float alpha, float resScale, int mode, int outBf16, int transC,
                 int ldct, int batch)
{
    dim3 grid((N + 127) / 128, (M + 127) / 128, batch);
    hgemm_kernel<<<grid, 256, SMEM_BYTES>>>(A, sA, B, sB, C, sC, bias, sBias, D, D2,
                                            M, N, K, lda, ldb, ldc, alpha, resScale, mode,
                                            outBf16, transC, ldct);
}

static void tconv(const float* in, bf16* out, int Ksrc, int N, int Kpad,
                  long long inStride, long long outStride, int batch)
{
    dim3 grid((Kpad + 31) / 32, (N + 31) / 32, batch);
    tconv_kernel<<<grid, dim3(32, 8)>>>(in, out, Ksrc, N, Kpad, inStride, outStride);
}

template <typename T>
static T* sym_addr(T* sym)
{
    void* p = nullptr;
    cudaGetSymbolAddress(&p, (const void*)sym);
    return (T*)p;
}

extern "C" void kernel_launch(void* const* d_in, const int* in_sizes, int n_in,
                              void* d_out, int out_size)
{
    cudaFuncSetAttribute(hgemm_kernel, cudaFuncAttributeMaxDynamicSharedMemorySize,
                         SMEM_BYTES);

    const int*   x   = (const int*)  d_in[0];
    const float* we  = (const float*)d_in[1];
    const float* pe  = (const float*)d_in[2];
    const float* Wq  = (const float*)d_in[3];
    const float* bq  = (const float*)d_in[4];
    const float* Wk  = (const float*)d_in[5];
    const float* bk  = (const float*)d_in[6];
    const float* Wv  = (const float*)d_in[7];
    const float* bv  = (const float*)d_in[8];
    const float* Wo  = (const float*)d_in[9];
    const float* bo  = (const float*)d_in[10];
    const float* g1  = (const float*)d_in[11];
    const float* be1 = (const float*)d_in[12];
    const float* g2  = (const float*)d_in[13];
    const float* be2 = (const float*)d_in[14];
    const float* W1  = (const float*)d_in[15];
    const float* bm1 = (const float*)d_in[16];
    const float* W2  = (const float*)d_in[17];
    const float* bm2 = (const float*)d_in[18];
    const float* gf  = (const float*)d_in[19];
    const float* bef = (const float*)d_in[20];
    const float* Wu  = (const float*)d_in[21];
    const float* bu  = (const float*)d_in[22];
    float* out = (float*)d_out;

    float* Y     = sym_addr(g_Y);
    float* zn    = sym_addr(g_zn);
    bf16*  xnb   = sym_addr(g_xnb);
    bf16*  znb   = sym_addr(g_znb);
    bf16*  Pb    = sym_addr(g_Pb);
    bf16*  S     = sym_addr(g_S);
    bf16*  vselT = sym_addr(g_vselT);
    bf16*  WselT = sym_addr(g_WselT);
    float* bsel  = sym_addr(g_bsel);
    bf16*  ya    = sym_addr(g_ya);
    bf16*  mlp   = sym_addr(g_mlp);
    bf16*  lg    = sym_addr(g_logits);
    bf16*  Wqc   = sym_addr(g_Wqc);
    bf16*  Wkc   = sym_addr(g_Wkc);
    bf16*  Mt    = sym_addr(g_Mt);
    float* wv    = sym_addr(g_w);
    float* cv    = sym_addr(g_c);
    bf16*  Wob   = sym_addr(g_Wob);
    bf16*  W1b   = sym_addr(g_W1b);
    bf16*  W2b   = sym_addr(g_W2b);
    bf16*  Wub   = sym_addr(g_Wub);

    const float inv_sqrt_de = 0.03608439182435161f;  // 1/sqrt(768)
    const long long WQK_N = (long long)NLAYERS * NH * DE * DE;  // 28.3M elems

    // ---- one-time per call: conversions + fused QK^T weight products ----
    convf2b_kernel<<<(int)((WQK_N / 4 + 255) / 256), 256>>>(Wq, Wqc, WQK_N);
    convf2b_kernel<<<(int)((WQK_N / 4 + 255) / 256), 256>>>(Wk, Wkc, WQK_N);
    wvec_kernel<<<(NLAYERS * NH * DE) / 8, 256>>>(Wk, bq, wv);
    // Mt[lh][d'][d] = sum_e Wk[lh][d'][e] * Wq[lh][d][e]   (batched, 48x 768^3)
    gemm(Wkc, (long long)DE * DE, Wqc, (long long)DE * DE,
         Mt, (long long)DE * DE, nullptr, 0, nullptr, nullptr,
         DE, DE, DE, DE, DE, DE, 1.0f, 0.0f, 0, 1, 0, 0, NLAYERS * NH);

    tconv(Wo, Wob, NSEL, DE, YCOLS, (long long)(NH * DV) * DE, (long long)DE * YCOLS, NLAYERS);
    tconv(W1, W1b, DE, DMLP, DE, (long long)DE * DMLP, (long long)DMLP * DE, NLAYERS);
    tconv(W2, W2b, DMLP, DE, DMLP, (long long)DMLP * DE, (long long)DE * DMLP, NLAYERS);
    tconv(Wu, Wub, DE, VOCAB, DE, 0, 0, 1);

    embed_kernel<<<(L * DE + 255) / 256, 256>>>(x, we, pe, Y);
    zero_ya_pad_kernel<<<(L * (YCOLS - NSEL) + 255) / 256, 256>>>(ya);

    for (int l = 0; l < NLAYERS; l++) {
        // xn = LN(Y; g1, be1) -> bf16
        ln_kernel<<<L, 256>>>(Y, xnb, nullptr, g1 + l * DE, be1 + l * DE);

        // c[h][m] = inv_sqrt_de * xn_m . (Wk_h bq_h)
        cvec_kernel<<<L, NH * 32>>>(xnb, wv + (long long)l * NH * DE, cv);

        // P_h = xn @ M_h  (batched over heads; replaces Q AND K projections)
        gemm(xnb, 0, Mt + (long long)l * NH * DE * DE, (long long)DE * DE,
             Pb, (long long)L * DE, nullptr, 0, nullptr, nullptr,
             L, DE, DE, DE, DE, DE, 1.0f, 0.0f, 0, 1, 0, 0, NH);

        // packed V projection -> vselT [YCOLS][L] (transposed store)
        pack_wsel_kernel<<<(YCOLS * DE + 255) / 256, 256>>>(Wv, bv, WselT, bsel, l);
        gemm(xnb, 0, WselT, 0, vselT, 0, bsel, 0, nullptr, nullptr,
             L, YCOLS, DE, DE, DE, 0, 1.0f, 0.0f, 0, 1, 1, L, 1);

        // S_h = inv_sqrt_de * P_h @ xn^T  (B shared across heads: sB = 0)
        gemm(Pb, (long long)L * DE, xnb, 0,
             S, (long long)L * L, nullptr, 0, nullptr, nullptr,
             L, L, DE, DE, DE, L, inv_sqrt_de, 0.0f, 0, 1, 0, 0, NH);

        // fused softmax(+c) + heads 0..10 attention dot; head 11 normalized in place
        softmax_attn_kernel<<<dim3(L, NH), 256>>>(S, vselT, cv, ya);

        // head 11: [L,64] = P11prob @ vselT[11:75]^T
        gemm(S + (long long)(NH - 1) * L * L, 0, vselT + (long long)(NH - 1) * L, 0,
             ya + (NH - 1), 0, nullptr, 0, nullptr, nullptr,
             L, DV, L, L, L, YCOLS, 1.0f, 0.0f, 0, 1, 0, 0, 1);

        // Y = 2*Y + (ya @ Wo^T + bo), K = 80 (cols 75..79 of ya are zero)
        gemm(ya, 0, Wob + (long long)l * DE * YCOLS, 0, Y, 0,
             bo + l * DE, 0, Y, nullptr,
             L, DE, YCOLS, YCOLS, YCOLS, DE, 1.0f, 2.0f, 2, 0, 0, 0, 1);

        // zn = LN(Y; g2, be2) -> fp32 + bf16
        ln_kernel<<<L, 256>>>(Y, znb, zn, g2 + l * DE, be2 + l * DE);

        // mlp = gelu(zn @ W1 + bm1) -> bf16
        gemm(znb, 0, W1b + (long long)l * DMLP * DE, 0, mlp, 0,
             bm1 + (long long)l * DMLP, 0, nullptr, nullptr,
             L, DMLP, DE, DE, DE, DMLP, 1.0f, 0.0f, 1, 1, 0, 0, 1);

        // Y = Y + zn + (mlp @ W2 + bm2)   (two-residual epilogue, mode 3)
        gemm(mlp, 0, W2b + (long long)l * DE * DMLP, 0, Y, 0,
             bm2 + l * DE, 0, Y, zn,
             L, DE, DMLP, DMLP, DMLP, DE, 1.0f, 1.0f, 3, 0, 0, 0, 1);
    }

    // final LN + vocab projection (bf16 logits) + softmax -> fp32 out
    ln_kernel<<<L, 256>>>(Y, xnb, nullptr, gf, bef);
    gemm(xnb, 0, Wub, 0, lg, 0, bu, 0, nullptr, nullptr,
         L, VOCAB, DE, DE, DE, VOCAB, 1.0f, 0.0f, 0, 1, 0, 0, 1);
    softmax_vocab_kernel<<<L, 256>>>(lg, out);
}